// round 6
// baseline (speedup 1.0000x reference)
#include <cuda_runtime.h>
#include <cuda_bf16.h>

// Problem constants
#define BB 65536
#define DD 256
#define KK 32
#define BD (BB * DD)

// Device scratch (no cudaMalloc allowed)
__device__ float g_uhat[KK * DD];   // [k][d]
__device__ float g_A[KK * KK];      // A[k][j] = w_k . uhat_j
__device__ float g_T[KK * BB];      // t values, [k][b] (coalesced writes+reads)

// ---------- f32x2 helpers ----------
__device__ __forceinline__ unsigned long long ffma2(unsigned long long a,
                                                    unsigned long long b,
                                                    unsigned long long c) {
    unsigned long long d;
    asm("fma.rn.f32x2 %0, %1, %2, %3;" : "=l"(d) : "l"(a), "l"(b), "l"(c));
    return d;
}
__device__ __forceinline__ unsigned long long packf2(float x, float y) {
    unsigned long long r;
    asm("mov.b64 %0, {%1, %2};" : "=l"(r) : "f"(x), "f"(y));
    return r;
}
__device__ __forceinline__ void unpackf2(unsigned long long v, float& lo, float& hi) {
    asm("mov.b64 {%0, %1}, %2;" : "=f"(lo), "=f"(hi) : "l"(v));
}

// fast accurate tanh: 1 - 2/(exp(2x)+1); __expf ~2ulp-ish, safe at +-inf
__device__ __forceinline__ float ftanh(float x) {
    float e = __expf(2.0f * x);
    return 1.0f - __fdividef(2.0f, e + 1.0f);
}

// ---------- Setup: uhat + A in ONE kernel (1 block, 1024 threads) ----------
// smem: ws[8192] linear w, uh[32*257] padded uhat, alpha[32]
#define SU_WS 0
#define SU_UH 8192
#define SU_AL (8192 + KK * 257)
#define SU_FLOATS (8192 + KK * 257 + 32)

__global__ __launch_bounds__(1024, 1)
void k_setup(const float* __restrict__ u, const float* __restrict__ w) {
    extern __shared__ float sm[];
    float* ws = sm + SU_WS;
    float* uh = sm + SU_UH;
    float* al = sm + SU_AL;
    const int t = threadIdx.x;

    // stage w linear, u padded (stride 257: conflict-free later)
    #pragma unroll
    for (int e = t; e < KK * DD; e += 1024) {
        int k = e >> 8, d = e & 255;
        ws[e] = w[e];
        uh[k * 257 + d] = u[e];
    }
    __syncthreads();

    // per-k reductions: warp g handles k=g
    {
        const int k = t >> 5, lane = t & 31;
        float p = 0.f, q = 0.f;
        #pragma unroll
        for (int i = 0; i < 8; ++i) {
            float wv = ws[k * DD + lane * 8 + i];
            float uv = uh[k * 257 + lane * 8 + i];
            p = fmaf(wv, uv, p);
            q = fmaf(wv, wv, q);
        }
        #pragma unroll
        for (int o = 16; o; o >>= 1) {
            p += __shfl_xor_sync(0xffffffffu, p, o);
            q += __shfl_xor_sync(0xffffffffu, q, o);
        }
        if (lane == 0) {
            float wu = p;
            float sp = fmaxf(wu, 0.f) + log1pf(expf(-fabsf(wu)));
            al[k] = (sp - 1.0f - wu) / q;
        }
    }
    __syncthreads();

    // uhat = u + alpha*w (in place in uh), also store to global
    #pragma unroll
    for (int e = t; e < KK * DD; e += 1024) {
        int k = e >> 8, d = e & 255;
        float v = fmaf(al[k], ws[e], uh[k * 257 + d]);
        uh[k * 257 + d] = v;
        g_uhat[e] = v;
    }
    __syncthreads();

    // A[k][j] = ws[k] . uh[j]  (warp = k, lane = j; ws broadcast, uh pad-257)
    {
        const int k = t >> 5, j = t & 31;
        float a0 = 0.f, a1 = 0.f, a2 = 0.f, a3 = 0.f;
        #pragma unroll 8
        for (int i = 0; i < DD; i += 4) {
            a0 = fmaf(ws[k * DD + i],     uh[j * 257 + i],     a0);
            a1 = fmaf(ws[k * DD + i + 1], uh[j * 257 + i + 1], a1);
            a2 = fmaf(ws[k * DD + i + 2], uh[j * 257 + i + 2], a2);
            a3 = fmaf(ws[k * DD + i + 3], uh[j * 257 + i + 3], a3);
        }
        g_A[k * KK + j] = (a0 + a1) + (a2 + a3);
    }
}

// ---------- K1: C = X.W^T fused with triangular recurrence ----------
// 64 rows/block, 256 threads, 2 blocks/SM.
// smem: XS transposed [d][r] stride 65 (16640), WT [d][k] stride 36 (9216),
//       CS [r][k] stride 33 (2112). Total 27968 fl = 111872 B.
#define K1_XS 0
#define K1_WT 16640
#define K1_CS (16640 + 9216)
#define K1_FLOATS (16640 + 9216 + 2112)

__global__ __launch_bounds__(256, 2)
void k1(const float* __restrict__ X, const float* __restrict__ w,
        const float* __restrict__ bvec, float* __restrict__ out) {
    extern __shared__ float sm[];
    float* XS = sm + K1_XS;
    float* WT = sm + K1_WT;
    float* CS = sm + K1_CS;

    const int t = threadIdx.x;
    const int r0 = blockIdx.x * 64;

    // stage X transposed [d][r] (coalesced loads, conflict-free stores), W [d][k]
    {
        const float* Xb = X + (size_t)r0 * DD;
        #pragma unroll
        for (int i = t; i < 64 * DD; i += 256) {
            int r = i >> 8, d = i & 255;
            XS[d * 65 + r] = Xb[i];
        }
        #pragma unroll
        for (int i = t; i < KK * DD; i += 256) {
            int k = i >> 8, d = i & 255;
            WT[d * 36 + k] = w[i];
        }
    }
    __syncthreads();

    // Phase 1: thread = (row, k-group of 8); full-d accumulation, no reduce
    {
        const int wp = t >> 5, lane = t & 31;
        const int rg = wp >> 2, kg = wp & 3;
        const int row = rg * 32 + lane;
        unsigned long long c0 = 0, c1 = 0, c2 = 0, c3 = 0;
        const float* xp = XS + row;
        const float* wtp = WT + kg * 8;
        #pragma unroll 16
        for (int d = 0; d < DD; ++d) {
            float x = xp[d * 65];
            unsigned long long xx = packf2(x, x);
            ulonglong2 wa = *(const ulonglong2*)(wtp + d * 36);
            ulonglong2 wb = *(const ulonglong2*)(wtp + d * 36 + 4);
            c0 = ffma2(xx, wa.x, c0);
            c1 = ffma2(xx, wa.y, c1);
            c2 = ffma2(xx, wb.x, c2);
            c3 = ffma2(xx, wb.y, c3);
        }
        float f0, f1;
        unpackf2(c0, f0, f1); CS[row * 33 + kg * 8 + 0] = f0; CS[row * 33 + kg * 8 + 1] = f1;
        unpackf2(c1, f0, f1); CS[row * 33 + kg * 8 + 2] = f0; CS[row * 33 + kg * 8 + 3] = f1;
        unpackf2(c2, f0, f1); CS[row * 33 + kg * 8 + 4] = f0; CS[row * 33 + kg * 8 + 5] = f1;
        unpackf2(c3, f0, f1); CS[row * 33 + kg * 8 + 6] = f0; CS[row * 33 + kg * 8 + 7] = f1;
    }
    __syncthreads();

    // Phase 2: triangular recurrence, one thread per row (t < 64)
    if (t < 64) {
        const int row = t;
        float tl[KK];
        #pragma unroll
        for (int k = 0; k < KK; ++k) {
            float lin = CS[row * 33 + k] + __ldg(&bvec[k]);
            #pragma unroll
            for (int j = 0; j < k; ++j)
                lin = fmaf(__ldg(&g_A[k * KK + j]), tl[j], lin);
            float tk = ftanh(lin);
            tl[k] = tk;
            g_T[k * BB + r0 + row] = tk;
            float akk = __ldg(&g_A[k * 33]);
            out[BD + k * BB + r0 + row] =
                logf(fabsf(fmaf(1.0f - tk * tk, akk, 1.0f)) + 1e-8f);
        }
    }
}

// ---------- K3: Z = X + T.Uhat ----------
// 128 rows/block, 512 blocks, 256 threads, 4 blocks/SM (single wave).
// smem: UH [k][d] 8192, TS [r][k] stride 36 (4608). 12800 fl = 51200 B.
#define K3_UH 0
#define K3_TS 8192
#define K3_FLOATS (8192 + 128 * 36)

__global__ __launch_bounds__(256, 4)
void k3(const float* __restrict__ X, float* __restrict__ out) {
    extern __shared__ float sm[];
    float* UH = sm + K3_UH;
    float* TS = sm + K3_TS;
    const int t = threadIdx.x;
    const int r0 = blockIdx.x * 128;

    #pragma unroll
    for (int i = t; i < KK * DD; i += 256) UH[i] = g_uhat[i];
    #pragma unroll
    for (int i = t; i < KK * 128; i += 256) {
        int k = i >> 7, r = i & 127;
        TS[r * 36 + k] = g_T[k * BB + r0 + r];
    }
    __syncthreads();

    const int lane = t & 31, wp = t >> 5;
    const int c0 = lane * 4, c1 = 128 + lane * 4;

    for (int g = 0; g < 4; ++g) {
        const int rb = wp * 16 + g * 4;
        ulonglong2 a[4][2];
        #pragma unroll
        for (int r = 0; r < 4; ++r) {
            const float* xr = X + (size_t)(r0 + rb + r) * DD;
            a[r][0] = *(const ulonglong2*)(xr + c0);
            a[r][1] = *(const ulonglong2*)(xr + c1);
        }
        #pragma unroll
        for (int kc = 0; kc < 8; ++kc) {
            float4 tv[4];
            #pragma unroll
            for (int r = 0; r < 4; ++r)
                tv[r] = *(const float4*)&TS[(rb + r) * 36 + kc * 4];
            #pragma unroll
            for (int kk = 0; kk < 4; ++kk) {
                const int k = kc * 4 + kk;
                ulonglong2 u0 = *(const ulonglong2*)&UH[k * DD + c0];
                ulonglong2 u1 = *(const ulonglong2*)&UH[k * DD + c1];
                #pragma unroll
                for (int r = 0; r < 4; ++r) {
                    float ts = (&tv[r].x)[kk];
                    unsigned long long tt = packf2(ts, ts);
                    a[r][0].x = ffma2(tt, u0.x, a[r][0].x);
                    a[r][0].y = ffma2(tt, u0.y, a[r][0].y);
                    a[r][1].x = ffma2(tt, u1.x, a[r][1].x);
                    a[r][1].y = ffma2(tt, u1.y, a[r][1].y);
                }
            }
        }
        #pragma unroll
        for (int r = 0; r < 4; ++r) {
            float* zr = out + (size_t)(r0 + rb + r) * DD;
            *(ulonglong2*)(zr + c0) = a[r][0];
            *(ulonglong2*)(zr + c1) = a[r][1];
        }
    }
}

extern "C" void kernel_launch(void* const* d_in, const int* in_sizes, int n_in,
                              void* d_out, int out_size) {
    const float* X = (const float*)d_in[0];
    // d_in[1] = h (unused)
    const float* u = (const float*)d_in[2];
    const float* w = (const float*)d_in[3];
    const float* b = (const float*)d_in[4];
    float* out = (float*)d_out;

    static bool attr_done = false;
    if (!attr_done) {
        cudaFuncSetAttribute(k_setup, cudaFuncAttributeMaxDynamicSharedMemorySize,
                             SU_FLOATS * (int)sizeof(float));
        cudaFuncSetAttribute(k1, cudaFuncAttributeMaxDynamicSharedMemorySize,
                             K1_FLOATS * (int)sizeof(float));
        cudaFuncSetAttribute(k3, cudaFuncAttributeMaxDynamicSharedMemorySize,
                             K3_FLOATS * (int)sizeof(float));
        attr_done = true;
    }

    k_setup<<<1, 1024, SU_FLOATS * sizeof(float)>>>(u, w);
    k1<<<BB / 64, 256, K1_FLOATS * sizeof(float)>>>(X, w, b, out);
    k3<<<BB / 128, 256, K3_FLOATS * sizeof(float)>>>(X, out);
}

// round 8
// speedup vs baseline: 3.3993x; 3.3993x over previous
#include <cuda_runtime.h>

// Problem constants
#define BB 65536
#define DD 256
#define KK 32
#define TM 32
#define NBLK (BB / TM)   // 2048
#define BD (BB * DD)

// Device scratch (no cudaMalloc allowed)
__device__ float g_G1[KK * KK];    // W . U^T
__device__ float g_G2[KK * KK];    // W . W^T
__device__ float g_uhat[KK * DD];  // [k][d]

// ---------- f32x2 helpers ----------
__device__ __forceinline__ unsigned long long ffma2(unsigned long long a,
                                                    unsigned long long b,
                                                    unsigned long long c) {
    unsigned long long d;
    asm("fma.rn.f32x2 %0, %1, %2, %3;" : "=l"(d) : "l"(a), "l"(b), "l"(c));
    return d;
}
__device__ __forceinline__ unsigned long long packf2(float x, float y) {
    unsigned long long r;
    asm("mov.b64 %0, {%1, %2};" : "=l"(r) : "f"(x), "f"(y));
    return r;
}

// fast accurate tanh: 1 - 2/(exp(2x)+1)
__device__ __forceinline__ float ftanh(float x) {
    float e = __expf(2.0f * x);
    return 1.0f - __fdividef(2.0f, e + 1.0f);
}

__device__ __forceinline__ float softplus(float x) {
    return fmaxf(x, 0.f) + log1pf(expf(-fabsf(x)));
}

// ---------- Gram kernel: G1[k][:], G2[k][:], uhat_k  (block = k) ----------
__global__ __launch_bounds__(256, 4)
void k_gram(const float* __restrict__ u, const float* __restrict__ w) {
    __shared__ float ws[DD];
    __shared__ float sdiag[2];
    const int k = blockIdx.x, t = threadIdx.x;
    ws[t] = w[k * DD + t];
    __syncthreads();

    const int j = t >> 3, s = t & 7;
    {
        const float* up  = u + j * DD + s * 32;
        const float* wp2 = w + j * DD + s * 32;
        const float* wsp = ws + s * 32;
        float p1 = 0.f, p2 = 0.f;
        #pragma unroll
        for (int i = 0; i < 32; ++i) {
            float wv = wsp[i];
            p1 = fmaf(wv, up[i], p1);
            p2 = fmaf(wv, wp2[i], p2);
        }
        #pragma unroll
        for (int o = 1; o <= 4; o <<= 1) {
            p1 += __shfl_xor_sync(0xffffffffu, p1, o);
            p2 += __shfl_xor_sync(0xffffffffu, p2, o);
        }
        if (s == 0) {
            g_G1[k * KK + j] = p1;
            g_G2[k * KK + j] = p2;
            if (j == k) { sdiag[0] = p1; sdiag[1] = p2; }
        }
    }
    __syncthreads();

    float wu = sdiag[0], ww = sdiag[1];
    float alpha = (softplus(wu) - 1.0f - wu) / ww;
    g_uhat[k * DD + t] = fmaf(alpha, ws[t], u[k * DD + t]);
}

// ---------- Main monolith ----------
// smem (floats):
//  XS : 0      X tile [r][d] stride 260 (float4-aligned, conflict-free) = 8320
//  WU : 8320   phase1: W^T [d][k] (stride 32);  phase>=2: uhat [k][d]   = 8192
//  AS : 16512  A[k][j] stride 32                                        = 1024
//  CS : 17536  C [r][k] stride 34 (8B-aligned f32x2 stores)             = 1088
//  TS : 18624  t [r][k] stride 36 (float4-aligned reads)                = 1152
//  AL : 19776  alpha[32]
//  BS : 19808  b[32]
// total 19840 floats = 79360 B  -> 2 blocks/SM
#define OFF_XS 0
#define OFF_WU 8320
#define OFF_AS 16512
#define OFF_CS 17536
#define OFF_TS 18624
#define OFF_AL 19776
#define OFF_BS 19808
#define SMEM_FLOATS 19840

__global__ __launch_bounds__(256, 2)
void nf_main(const float* __restrict__ X, const float* __restrict__ w,
             const float* __restrict__ bvec, float* __restrict__ out) {
    extern __shared__ float sm[];
    float* XS = sm + OFF_XS;
    float* WU = sm + OFF_WU;
    float* AS = sm + OFF_AS;
    float* CS = sm + OFF_CS;
    float* TS = sm + OFF_TS;
    float* AL = sm + OFF_AL;
    float* BS = sm + OFF_BS;

    const int t = threadIdx.x;
    const int r0 = blockIdx.x * TM;

    // ---- Prologue: stage X, W^T, alpha, b ----
    {
        const float* Xb = X + (size_t)r0 * DD;
        #pragma unroll
        for (int i = t; i < TM * DD; i += 256) {
            int r = i >> 8, d = i & 255;
            XS[r * 260 + d] = Xb[i];
        }
        #pragma unroll
        for (int i = t; i < KK * DD; i += 256) {
            int k = i >> 8, d = i & 255;
            WU[d * 32 + k] = w[i];
        }
        if (t < KK) {
            float wu = g_G1[t * (KK + 1)];
            float ww = g_G2[t * (KK + 1)];
            AL[t] = (softplus(wu) - 1.0f - wu) / ww;
            BS[t] = bvec[t];
        }
    }
    __syncthreads();

    // A = G1 + alpha_j * G2 (tiny; AS consumed only after next barrier)
    #pragma unroll
    for (int e = t; e < KK * KK; e += 256)
        AS[e] = g_G1[e] + AL[e & 31] * g_G2[e];

    // ---- Phase 1: C = X . W^T ; warp wp owns k-range [4wp,4wp+4), lane = row ----
    {
        const int wp = t >> 5, lane = t & 31;
        unsigned long long c0 = 0ull, c1 = 0ull;
        const float* xrow = XS + lane * 260;
        const float* wcol = WU + wp * 4;
        #pragma unroll 8
        for (int d = 0; d < DD; d += 4) {
            float4 xv = *(const float4*)(xrow + d);
            ulonglong2 w0 = *(const ulonglong2*)(wcol + (d + 0) * 32);
            ulonglong2 w1 = *(const ulonglong2*)(wcol + (d + 1) * 32);
            ulonglong2 w2 = *(const ulonglong2*)(wcol + (d + 2) * 32);
            ulonglong2 w3 = *(const ulonglong2*)(wcol + (d + 3) * 32);
            c0 = ffma2(packf2(xv.x, xv.x), w0.x, c0);
            c1 = ffma2(packf2(xv.x, xv.x), w0.y, c1);
            c0 = ffma2(packf2(xv.y, xv.y), w1.x, c0);
            c1 = ffma2(packf2(xv.y, xv.y), w1.y, c1);
            c0 = ffma2(packf2(xv.z, xv.z), w2.x, c0);
            c1 = ffma2(packf2(xv.z, xv.z), w2.y, c1);
            c0 = ffma2(packf2(xv.w, xv.w), w3.x, c0);
            c1 = ffma2(packf2(xv.w, xv.w), w3.y, c1);
        }
        *(unsigned long long*)&CS[lane * 34 + wp * 4]     = c0;
        *(unsigned long long*)&CS[lane * 34 + wp * 4 + 2] = c1;
    }
    __syncthreads();

    // ---- Phase 2: warp 0 = triangular recurrence; warps 1-7 stage uhat over WU ----
    if (t < TM) {
        const int row = t;
        float tl[KK];
        #pragma unroll
        for (int k = 0; k < KK; ++k) {
            float lin = CS[row * 34 + k] + BS[k];
            #pragma unroll
            for (int j = 0; j < k; ++j)
                lin = fmaf(AS[k * KK + j], tl[j], lin);
            float tk = ftanh(lin);
            tl[k] = tk;
            TS[row * 36 + k] = tk;
            float akk = AS[k * (KK + 1)];
            out[BD + k * BB + r0 + row] =
                logf(fabsf(fmaf(1.0f - tk * tk, akk, 1.0f)) + 1e-8f);
        }
    } else {
        for (int i = t - TM; i < KK * DD; i += 256 - TM)
            WU[i] = g_uhat[i];
    }
    __syncthreads();

    // ---- Phase 3: Z = X + T . Uhat ----
    {
        const int lane = t & 31, wp = t >> 5;
        const int c0 = lane * 4, c1 = 128 + lane * 4;
        const int rb = wp * 4;
        ulonglong2 a[4][2];
        #pragma unroll
        for (int r = 0; r < 4; ++r) {
            a[r][0] = *(const ulonglong2*)&XS[(rb + r) * 260 + c0];
            a[r][1] = *(const ulonglong2*)&XS[(rb + r) * 260 + c1];
        }
        #pragma unroll
        for (int kc = 0; kc < 8; ++kc) {
            float4 tv[4];
            #pragma unroll
            for (int r = 0; r < 4; ++r)
                tv[r] = *(const float4*)&TS[(rb + r) * 36 + kc * 4];
            #pragma unroll
            for (int kk = 0; kk < 4; ++kk) {
                const int k = kc * 4 + kk;
                ulonglong2 u0 = *(const ulonglong2*)&WU[k * DD + c0];
                ulonglong2 u1 = *(const ulonglong2*)&WU[k * DD + c1];
                #pragma unroll
                for (int r = 0; r < 4; ++r) {
                    float ts = (&tv[r].x)[kk];
                    unsigned long long tt = packf2(ts, ts);
                    a[r][0].x = ffma2(tt, u0.x, a[r][0].x);
                    a[r][0].y = ffma2(tt, u0.y, a[r][0].y);
                    a[r][1].x = ffma2(tt, u1.x, a[r][1].x);
                    a[r][1].y = ffma2(tt, u1.y, a[r][1].y);
                }
            }
        }
        #pragma unroll
        for (int r = 0; r < 4; ++r) {
            float* zr = out + (size_t)(r0 + rb + r) * DD;
            *(ulonglong2*)(zr + c0) = a[r][0];
            *(ulonglong2*)(zr + c1) = a[r][1];
        }
    }
}

extern "C" void kernel_launch(void* const* d_in, const int* in_sizes, int n_in,
                              void* d_out, int out_size) {
    const float* X = (const float*)d_in[0];
    // d_in[1] = h (unused)
    const float* u = (const float*)d_in[2];
    const float* w = (const float*)d_in[3];
    const float* b = (const float*)d_in[4];
    float* out = (float*)d_out;

    cudaFuncSetAttribute(nf_main, cudaFuncAttributeMaxDynamicSharedMemorySize,
                         SMEM_FLOATS * (int)sizeof(float));

    k_gram<<<KK, 256>>>(u, w);
    nf_main<<<NBLK, 256, SMEM_FLOATS * sizeof(float)>>>(X, w, b, out);
}

// round 9
// speedup vs baseline: 3.7244x; 1.0956x over previous
#include <cuda_runtime.h>

// Problem constants
#define BB 65536
#define DD 256
#define KK 32
#define TM 32
#define NBLK (BB / TM)   // 2048
#define BD (BB * DD)

// Device scratch (no cudaMalloc allowed)
__device__ float g_G1[KK * KK];    // W . U^T
__device__ float g_G2[KK * KK];    // W . W^T
__device__ float g_uhat[KK * DD];  // [k][d]

// ---------- f32x2 helpers ----------
__device__ __forceinline__ unsigned long long ffma2(unsigned long long a,
                                                    unsigned long long b,
                                                    unsigned long long c) {
    unsigned long long d;
    asm("fma.rn.f32x2 %0, %1, %2, %3;" : "=l"(d) : "l"(a), "l"(b), "l"(c));
    return d;
}
__device__ __forceinline__ unsigned long long packf2(float x, float y) {
    unsigned long long r;
    asm("mov.b64 %0, {%1, %2};" : "=l"(r) : "f"(x), "f"(y));
    return r;
}

// fast accurate tanh: 1 - 2/(exp(2x)+1)
__device__ __forceinline__ float ftanh(float x) {
    float e = __expf(2.0f * x);
    return 1.0f - __fdividef(2.0f, e + 1.0f);
}

__device__ __forceinline__ float softplus(float x) {
    return fmaxf(x, 0.f) + log1pf(expf(-fabsf(x)));
}

// ---------- Gram kernel: G1[k][:], G2[k][:], uhat_k  (block = k) ----------
__global__ __launch_bounds__(256, 4)
void k_gram(const float* __restrict__ u, const float* __restrict__ w) {
    __shared__ float ws[DD];
    __shared__ float sdiag[2];
    const int k = blockIdx.x, t = threadIdx.x;
    ws[t] = w[k * DD + t];
    __syncthreads();

    const int j = t >> 3, s = t & 7;
    {
        const float* up  = u + j * DD + s * 32;
        const float* wp2 = w + j * DD + s * 32;
        const float* wsp = ws + s * 32;
        float p1 = 0.f, p2 = 0.f;
        #pragma unroll
        for (int i = 0; i < 32; ++i) {
            float wv = wsp[i];
            p1 = fmaf(wv, up[i], p1);
            p2 = fmaf(wv, wp2[i], p2);
        }
        #pragma unroll
        for (int o = 1; o <= 4; o <<= 1) {
            p1 += __shfl_xor_sync(0xffffffffu, p1, o);
            p2 += __shfl_xor_sync(0xffffffffu, p2, o);
        }
        if (s == 0) {
            g_G1[k * KK + j] = p1;
            g_G2[k * KK + j] = p2;
            if (j == k) { sdiag[0] = p1; sdiag[1] = p2; }
        }
    }
    __syncthreads();

    float wu = sdiag[0], ww = sdiag[1];
    float alpha = (softplus(wu) - 1.0f - wu) / ww;
    g_uhat[k * DD + t] = fmaf(alpha, ws[t], u[k * DD + t]);
}

// ---------- Main monolith ----------
// smem (floats):
//  XS : 0      X tile [r][d] stride 260 (float4-aligned, conflict-free) = 8320
//  WU : 8320   phase1: W^T [d][k] stride 36; phase>=2: uhat [k][d] lin  = 9216
//  AS : 17536  A[k][j] stride 32                                        = 1024
//  CS : 18560  C [r][k] stride 34 (8B-aligned f32x2 stores)             = 1088
//  TS : 19648  t [r][k] stride 36 (float4-aligned reads)                = 1152
//  AL : 20800  alpha[32]
//  BS : 20832  b[32]
// total 20864 floats = 83456 B -> 2 blocks/SM
#define OFF_XS 0
#define OFF_WU 8320
#define OFF_AS 17536
#define OFF_CS 18560
#define OFF_TS 19648
#define OFF_AL 20800
#define OFF_BS 20832
#define SMEM_FLOATS 20864

__global__ __launch_bounds__(256, 2)
void nf_main(const float* __restrict__ X, const float* __restrict__ w,
             const float* __restrict__ bvec, float* __restrict__ out) {
    extern __shared__ float sm[];
    float* XS = sm + OFF_XS;
    float* WU = sm + OFF_WU;
    float* AS = sm + OFF_AS;
    float* CS = sm + OFF_CS;
    float* TS = sm + OFF_TS;
    float* AL = sm + OFF_AL;
    float* BS = sm + OFF_BS;

    const int t = threadIdx.x;
    const int r0 = blockIdx.x * TM;

    // ---- Prologue: stage X (float4, conflict-free), W^T (stride 36), alpha, b ----
    {
        const float4* Xb4 = (const float4*)(X + (size_t)r0 * DD);
        #pragma unroll
        for (int i = t; i < TM * DD / 4; i += 256) {
            int r = i >> 6, d4 = i & 63;           // 64 float4 per row
            *(float4*)&XS[r * 260 + d4 * 4] = Xb4[i];
        }
        #pragma unroll
        for (int i = t; i < KK * DD; i += 256) {
            int k = i >> 8, d = i & 255;
            WU[d * 36 + k] = w[i];                 // 4-way conflict max (bank 4d+k)
        }
        if (t < KK) {
            float wu = g_G1[t * (KK + 1)];
            float ww = g_G2[t * (KK + 1)];
            AL[t] = (softplus(wu) - 1.0f - wu) / ww;
            BS[t] = bvec[t];
        }
    }
    __syncthreads();

    // A = G1 + alpha_j * G2 (consumed after next barrier)
    #pragma unroll
    for (int e = t; e < KK * KK; e += 256)
        AS[e] = g_G1[e] + AL[e & 31] * g_G2[e];

    // ---- Phase 1: C = X . W^T ; warp wp owns k-range [4wp,4wp+4), lane = row ----
    {
        const int wp = t >> 5, lane = t & 31;
        unsigned long long c0 = 0ull, c1 = 0ull;
        const float* xrow = XS + lane * 260;
        const float* wcol = WU + wp * 4;
        #pragma unroll 8
        for (int d = 0; d < DD; d += 4) {
            float4 xv = *(const float4*)(xrow + d);
            ulonglong2 w0 = *(const ulonglong2*)(wcol + (d + 0) * 36);
            ulonglong2 w1 = *(const ulonglong2*)(wcol + (d + 1) * 36);
            ulonglong2 w2 = *(const ulonglong2*)(wcol + (d + 2) * 36);
            ulonglong2 w3 = *(const ulonglong2*)(wcol + (d + 3) * 36);
            c0 = ffma2(packf2(xv.x, xv.x), w0.x, c0);
            c1 = ffma2(packf2(xv.x, xv.x), w0.y, c1);
            c0 = ffma2(packf2(xv.y, xv.y), w1.x, c0);
            c1 = ffma2(packf2(xv.y, xv.y), w1.y, c1);
            c0 = ffma2(packf2(xv.z, xv.z), w2.x, c0);
            c1 = ffma2(packf2(xv.z, xv.z), w2.y, c1);
            c0 = ffma2(packf2(xv.w, xv.w), w3.x, c0);
            c1 = ffma2(packf2(xv.w, xv.w), w3.y, c1);
        }
        *(unsigned long long*)&CS[lane * 34 + wp * 4]     = c0;
        *(unsigned long long*)&CS[lane * 34 + wp * 4 + 2] = c1;
    }
    __syncthreads();

    // ---- Phase 2: warp 0 = triangular recurrence; warps 1-7 stage uhat over WU ----
    if (t < TM) {
        const int row = t;
        float tl[KK];
        #pragma unroll
        for (int k = 0; k < KK; ++k) {
            float lin = CS[row * 34 + k] + BS[k];
            #pragma unroll
            for (int j = 0; j < k; ++j)
                lin = fmaf(AS[k * KK + j], tl[j], lin);
            float tk = ftanh(lin);
            tl[k] = tk;
            TS[row * 36 + k] = tk;
            float akk = AS[k * (KK + 1)];
            out[BD + k * BB + r0 + row] =
                __logf(fabsf(fmaf(1.0f - tk * tk, akk, 1.0f)) + 1e-8f);
        }
    } else {
        const float4* U4 = (const float4*)g_uhat;
        float4* WU4 = (float4*)WU;
        for (int i = t - TM; i < KK * DD / 4; i += 256 - TM)
            WU4[i] = U4[i];
    }
    __syncthreads();

    // ---- Phase 3: Z = X + T . Uhat ----
    {
        const int lane = t & 31, wp = t >> 5;
        const int c0 = lane * 4, c1 = 128 + lane * 4;
        const int rb = wp * 4;
        ulonglong2 a[4][2];
        #pragma unroll
        for (int r = 0; r < 4; ++r) {
            a[r][0] = *(const ulonglong2*)&XS[(rb + r) * 260 + c0];
            a[r][1] = *(const ulonglong2*)&XS[(rb + r) * 260 + c1];
        }
        #pragma unroll
        for (int kc = 0; kc < 8; ++kc) {
            float4 tv[4];
            #pragma unroll
            for (int r = 0; r < 4; ++r)
                tv[r] = *(const float4*)&TS[(rb + r) * 36 + kc * 4];
            #pragma unroll
            for (int kk = 0; kk < 4; ++kk) {
                const int k = kc * 4 + kk;
                ulonglong2 u0 = *(const ulonglong2*)&WU[k * DD + c0];
                ulonglong2 u1 = *(const ulonglong2*)&WU[k * DD + c1];
                #pragma unroll
                for (int r = 0; r < 4; ++r) {
                    float ts = (&tv[r].x)[kk];
                    unsigned long long tt = packf2(ts, ts);
                    a[r][0].x = ffma2(tt, u0.x, a[r][0].x);
                    a[r][0].y = ffma2(tt, u0.y, a[r][0].y);
                    a[r][1].x = ffma2(tt, u1.x, a[r][1].x);
                    a[r][1].y = ffma2(tt, u1.y, a[r][1].y);
                }
            }
        }
        #pragma unroll
        for (int r = 0; r < 4; ++r) {
            float* zr = out + (size_t)(r0 + rb + r) * DD;
            *(ulonglong2*)(zr + c0) = a[r][0];
            *(ulonglong2*)(zr + c1) = a[r][1];
        }
    }
}

extern "C" void kernel_launch(void* const* d_in, const int* in_sizes, int n_in,
                              void* d_out, int out_size) {
    const float* X = (const float*)d_in[0];
    // d_in[1] = h (unused)
    const float* u = (const float*)d_in[2];
    const float* w = (const float*)d_in[3];
    const float* b = (const float*)d_in[4];
    float* out = (float*)d_out;

    cudaFuncSetAttribute(nf_main, cudaFuncAttributeMaxDynamicSharedMemorySize,
                         SMEM_FLOATS * (int)sizeof(float));

    k_gram<<<KK, 256>>>(u, w);
    nf_main<<<NBLK, 256, SMEM_FLOATS * sizeof(float)>>>(X, w, b, out);
}